// round 1
// baseline (speedup 1.0000x reference)
#include <cuda_runtime.h>
#include <math.h>

#define Bn   2
#define Sn   2048
#define En   512
#define Hn   8
#define DHn  64
#define HIDn 2048
#define OUTn 6
#define Wn   5
#define SKn  2044          // S - W + 1
#define BSn  (Bn*Sn)       // 4096
#define NBH  (Bn*Hn)       // 16
#define NCHUNK 128

// ---------------- scratch (static device globals; no runtime alloc) ----------
__device__ float g_x [BSn*En];                    // current activations [B*S, E]
__device__ float g_x2[BSn*En];                    // temp (attn out / ffn out)
__device__ float g_q [NBH*Sn*DHn];                // [bh, s, dh]
__device__ float g_k [NBH*Sn*DHn];
__device__ float g_v [NBH*Sn*DHn];
__device__ float g_vs[NBH*SKn*DHn];               // window-summed V
__device__ float g_qk[(size_t)NBH*Sn*Sn];         // full QK^T   (268 MB)
__device__ float g_a [(size_t)NBH*Sn*Sn];         // softmax(A)  (268 MB, ld=Sn)
__device__ float g_h [BSn*HIDn];                  // ffn hidden
__device__ float g_part[Bn*NCHUNK*OUTn];          // final-gemm partials

// ---------------- embedding + positional encoding ----------------------------
__global__ void embed_kernel(const int* __restrict__ inputs,
                             const float* __restrict__ emb)
{
    int row = blockIdx.x;                 // b*S + s
    int s   = row % Sn;
    int tok = inputs[row];
    const float coef = -9.210340371976184f / (float)En;   // -ln(10000)/E
    for (int e = threadIdx.x; e < En; e += blockDim.x) {
        float freq = expf((float)(e & ~1) * coef);
        float ang  = (float)s * freq;
        float pe   = (e & 1) ? cosf(ang) : sinf(ang);
        g_x[(size_t)row*En + e] = emb[(size_t)tok*En + e] + pe;
    }
}

// ---------------- generic tiled SGEMM (NN), batched, fused epilogues ---------
// modes: 2 = bias+relu  (ffn1)
//        3 = bias+residual (ffn2)
//        4 = bias + QKV scatter to [b,h,s,dh]
//        5 = attn-out scatter to [b,s,h*dh] (no bias)
__global__ void __launch_bounds__(256)
gemm_nn(const float* __restrict__ Ab, int lda, long long sA,
        const float* __restrict__ Bb, int ldb, long long sB,
        float* __restrict__ Cb, int ldc,
        const float* __restrict__ bias,
        const float* __restrict__ res,
        int M, int N, int K, int mode)
{
    __shared__ float As[16][65];
    __shared__ float Bs[16][64];
    int z  = blockIdx.z;
    const float* A = Ab + (size_t)z * sA;
    const float* B = Bb + (size_t)z * sB;
    int tid = threadIdx.x;
    int tx = tid & 15, ty = tid >> 4;
    int bm = blockIdx.y * 64, bn = blockIdx.x * 64;
    float acc[4][4] = {};

    for (int k0 = 0; k0 < K; k0 += 16) {
        #pragma unroll
        for (int i = tid; i < 1024; i += 256) {
            int r = i >> 4, c = i & 15;
            int kk = k0 + c;
            As[c][r] = (kk < K) ? A[(size_t)(bm + r) * lda + kk] : 0.f;
        }
        #pragma unroll
        for (int i = tid; i < 1024; i += 256) {
            int r = i >> 6, c = i & 63;
            int kk = k0 + r;
            Bs[r][c] = (kk < K) ? B[(size_t)kk * ldb + bn + c] : 0.f;
        }
        __syncthreads();
        #pragma unroll
        for (int kk = 0; kk < 16; kk++) {
            float a[4], bb[4];
            #pragma unroll
            for (int i = 0; i < 4; i++) a[i]  = As[kk][ty*4+i];
            #pragma unroll
            for (int j = 0; j < 4; j++) bb[j] = Bs[kk][tx*4+j];
            #pragma unroll
            for (int i = 0; i < 4; i++)
                #pragma unroll
                for (int j = 0; j < 4; j++)
                    acc[i][j] += a[i] * bb[j];
        }
        __syncthreads();
    }

    int b0 = 0, h0 = 0;
    if (mode == 5) { b0 = z / Hn; h0 = z % Hn; }
    #pragma unroll
    for (int i = 0; i < 4; i++) {
        int r = bm + ty*4 + i;
        #pragma unroll
        for (int j = 0; j < 4; j++) {
            int c = bn + tx*4 + j;
            float vv = acc[i][j];
            if (mode == 2) {
                vv += bias[c]; vv = fmaxf(vv, 0.f);
                Cb[(size_t)r*ldc + c] = vv;
            } else if (mode == 3) {
                vv += bias[c] + res[(size_t)r*ldc + c];
                Cb[(size_t)r*ldc + c] = vv;
            } else if (mode == 4) {
                vv += bias[c];
                int b = r / Sn, s = r % Sn, h = c / DHn, d = c % DHn;
                Cb[((size_t)(b*Hn + h)*Sn + s)*DHn + d] = vv;
            } else { // mode 5
                Cb[((size_t)(b0*Sn) + r)*En + h0*DHn + c] = vv;
            }
        }
    }
}

// ---------------- batched QK^T (NT, K=64, full depth in one tile) ------------
__global__ void __launch_bounds__(256) qk_gemm()
{
    __shared__ float Qs[64][65];   // [d][q]
    __shared__ float Ks[64][65];   // [d][t]
    int z  = blockIdx.z;
    const float* Q  = g_q + (size_t)z * Sn * DHn;
    const float* Km = g_k + (size_t)z * Sn * DHn;
    float* C        = g_qk + (size_t)z * Sn * Sn;
    int tid = threadIdx.x;
    int tx = tid & 15, ty = tid >> 4;
    int q0 = blockIdx.y * 64, t0 = blockIdx.x * 64;

    #pragma unroll
    for (int i = tid; i < 4096; i += 256) {
        int r = i >> 6, d = i & 63;
        Qs[d][r] = Q[(size_t)(q0 + r)*DHn + d];
    }
    #pragma unroll
    for (int i = tid; i < 4096; i += 256) {
        int r = i >> 6, d = i & 63;
        Ks[d][r] = Km[(size_t)(t0 + r)*DHn + d];
    }
    __syncthreads();

    float acc[4][4] = {};
    #pragma unroll
    for (int d = 0; d < 64; d++) {
        float a[4], b[4];
        #pragma unroll
        for (int i = 0; i < 4; i++) a[i] = Qs[d][ty*4+i];
        #pragma unroll
        for (int j = 0; j < 4; j++) b[j] = Ks[d][tx*4+j];
        #pragma unroll
        for (int i = 0; i < 4; i++)
            #pragma unroll
            for (int j = 0; j < 4; j++)
                acc[i][j] += a[i] * b[j];
    }
    #pragma unroll
    for (int i = 0; i < 4; i++)
        #pragma unroll
        for (int j = 0; j < 4; j++)
            C[(size_t)(q0 + ty*4 + i)*Sn + (t0 + tx*4 + j)] = acc[i][j];
}

// ---------------- window-sum (5 shifted diagonals) + softmax -----------------
__global__ void win_softmax()
{
    int q  = blockIdx.x;
    int bh = blockIdx.y;
    const float* qk = g_qk + (size_t)bh * Sn * Sn;
    float* arow     = g_a  + (size_t)bh * Sn * Sn + (size_t)q * Sn;
    __shared__ float row[SKn];
    __shared__ float red[256];
    int tid = threadIdx.x;

    float lmax = -1e30f;
    for (int t = tid; t < SKn; t += 256) {
        float s = 0.f;
        #pragma unroll
        for (int j = 0; j < Wn; j++) {
            int qi = q + j - 2;
            if (qi >= 0 && qi < Sn) s += qk[(size_t)qi*Sn + (t + j)];
        }
        s *= 0.125f;      // DH^-0.5
        row[t] = s;
        lmax = fmaxf(lmax, s);
    }
    red[tid] = lmax; __syncthreads();
    for (int o = 128; o > 0; o >>= 1) {
        if (tid < o) red[tid] = fmaxf(red[tid], red[tid+o]);
        __syncthreads();
    }
    float m = red[0]; __syncthreads();

    float lsum = 0.f;
    for (int t = tid; t < SKn; t += 256) {
        float e = __expf(row[t] - m);
        row[t] = e;
        lsum += e;
    }
    red[tid] = lsum; __syncthreads();
    for (int o = 128; o > 0; o >>= 1) {
        if (tid < o) red[tid] += red[tid+o];
        __syncthreads();
    }
    float inv = 1.f / red[0];
    for (int t = tid; t < SKn; t += 256) arow[t] = row[t] * inv;
}

// ---------------- V window pre-sum -------------------------------------------
__global__ void vsum_kernel()
{
    int idx = blockIdx.x * 256 + threadIdx.x;
    if (idx >= NBH*SKn*DHn) return;
    int d  = idx % DHn;
    int t  = (idx / DHn) % SKn;
    int bh = idx / (DHn*SKn);
    const float* v = g_v + (size_t)bh * Sn * DHn;
    float s = 0.f;
    #pragma unroll
    for (int j = 0; j < Wn; j++) s += v[(size_t)(t + j)*DHn + d];
    g_vs[idx] = s;
}

// ---------------- layernorm (E = 512) ----------------------------------------
__global__ void layernorm_kernel(const float* __restrict__ in,
                                 float* __restrict__ out,
                                 const float* __restrict__ w,
                                 const float* __restrict__ b)
{
    int row = blockIdx.x;
    int tid = threadIdx.x;
    const float* xr = in + (size_t)row * En;
    float v0 = xr[tid], v1 = xr[tid + 256];
    __shared__ float s1[256], s2[256];
    s1[tid] = v0 + v1;
    s2[tid] = v0*v0 + v1*v1;
    __syncthreads();
    for (int o = 128; o > 0; o >>= 1) {
        if (tid < o) { s1[tid] += s1[tid+o]; s2[tid] += s2[tid+o]; }
        __syncthreads();
    }
    float mean = s1[0] * (1.f/En);
    float var  = s2[0] * (1.f/En) - mean*mean;
    float rstd = rsqrtf(var + 1e-5f);
    float* orow = out + (size_t)row * En;
    orow[tid]       = (v0 - mean) * rstd * w[tid]       + b[tid];
    orow[tid + 256] = (v1 - mean) * rstd * w[tid + 256] + b[tid + 256];
}

// ---------------- final projection x[B, S*E] @ out_w[S*E, 6] -----------------
__global__ void out_stage1(const float* __restrict__ out_w)
{
    int b = blockIdx.y, chunk = blockIdx.x;
    int tid = threadIdx.x;
    const int CH = Sn*En / NCHUNK;               // 8192
    const float* xr = g_x + (size_t)b*Sn*En + (size_t)chunk*CH;
    const float* wr = out_w + (size_t)chunk*CH*OUTn;
    float acc[OUTn] = {};
    for (int i = tid; i < CH; i += 256) {
        float xv = xr[i];
        #pragma unroll
        for (int o = 0; o < OUTn; o++) acc[o] += xv * wr[(size_t)i*OUTn + o];
    }
    __shared__ float red[OUTn*256];
    #pragma unroll
    for (int o = 0; o < OUTn; o++) red[o*256 + tid] = acc[o];
    __syncthreads();
    for (int st = 128; st > 0; st >>= 1) {
        if (tid < st)
            #pragma unroll
            for (int o = 0; o < OUTn; o++)
                red[o*256 + tid] += red[o*256 + tid + st];
        __syncthreads();
    }
    if (tid < OUTn) g_part[(b*NCHUNK + chunk)*OUTn + tid] = red[tid*256];
}

__global__ void out_stage2(const float* __restrict__ out_b,
                           float* __restrict__ out)
{
    int tid = threadIdx.x;
    if (tid < Bn*OUTn) {
        int b = tid / OUTn, o = tid % OUTn;
        float s = out_b[o];
        for (int c = 0; c < NCHUNK; c++)
            s += g_part[(b*NCHUNK + c)*OUTn + o];
        out[tid] = s;
    }
}

// ---------------- driver ------------------------------------------------------
extern "C" void kernel_launch(void* const* d_in, const int* in_sizes, int n_in,
                              void* d_out, int out_size)
{
    const int*   inputs = (const int*)  d_in[0];
    const float* emb    = (const float*)d_in[1];
    const float* ln_w   = (const float*)d_in[2];
    const float* ln_b   = (const float*)d_in[3];
    const float* q_w    = (const float*)d_in[4];
    const float* q_b    = (const float*)d_in[5];
    const float* k_w    = (const float*)d_in[6];
    const float* k_b    = (const float*)d_in[7];
    const float* v_w    = (const float*)d_in[8];
    const float* v_b    = (const float*)d_in[9];
    const float* fc1_w  = (const float*)d_in[10];
    const float* fc1_b  = (const float*)d_in[11];
    const float* fc2_w  = (const float*)d_in[12];
    const float* fc2_b  = (const float*)d_in[13];
    const float* out_w  = (const float*)d_in[14];
    const float* out_b  = (const float*)d_in[15];
    float* out = (float*)d_out;

    float *px, *px2, *pq, *pk, *pv, *pvs, *pqk, *pa, *ph;
    cudaGetSymbolAddress((void**)&px,  g_x);
    cudaGetSymbolAddress((void**)&px2, g_x2);
    cudaGetSymbolAddress((void**)&pq,  g_q);
    cudaGetSymbolAddress((void**)&pk,  g_k);
    cudaGetSymbolAddress((void**)&pv,  g_v);
    cudaGetSymbolAddress((void**)&pvs, g_vs);
    cudaGetSymbolAddress((void**)&pqk, g_qk);
    cudaGetSymbolAddress((void**)&pa,  g_a);
    cudaGetSymbolAddress((void**)&ph,  g_h);

    embed_kernel<<<BSn, 256>>>(inputs, emb);

    for (int l = 0; l < 6; l++) {
        dim3 gqkv(En/64, BSn/64, 1);
        gemm_nn<<<gqkv, 256>>>(px, En, 0, q_w, En, 0, pq, 0, q_b, nullptr,
                               BSn, En, En, 4);
        gemm_nn<<<gqkv, 256>>>(px, En, 0, k_w, En, 0, pk, 0, k_b, nullptr,
                               BSn, En, En, 4);
        gemm_nn<<<gqkv, 256>>>(px, En, 0, v_w, En, 0, pv, 0, v_b, nullptr,
                               BSn, En, En, 4);

        qk_gemm<<<dim3(Sn/64, Sn/64, NBH), 256>>>();
        win_softmax<<<dim3(Sn, NBH), 256>>>();
        vsum_kernel<<<(NBH*SKn*DHn + 255)/256, 256>>>();

        // O = A @ Vsum, scatter to [B,S,E]
        gemm_nn<<<dim3(1, Sn/64, NBH), 256>>>(pa, Sn, (long long)Sn*Sn,
                                              pvs, DHn, (long long)SKn*DHn,
                                              px2, 0, nullptr, nullptr,
                                              Sn, DHn, SKn, 5);

        layernorm_kernel<<<BSn, 256>>>(px2, px, ln_w, ln_b);

        gemm_nn<<<dim3(HIDn/64, BSn/64, 1), 256>>>(px, En, 0, fc1_w, HIDn, 0,
                                                   ph, HIDn, fc1_b, nullptr,
                                                   BSn, HIDn, En, 2);
        gemm_nn<<<dim3(En/64, BSn/64, 1), 256>>>(ph, HIDn, 0, fc2_w, En, 0,
                                                 px2, En, fc2_b, px,
                                                 BSn, En, HIDn, 3);

        layernorm_kernel<<<BSn, 256>>>(px2, px, ln_w, ln_b);
    }

    out_stage1<<<dim3(NCHUNK, Bn), 256>>>(out_w);
    out_stage2<<<1, 32>>>(out_b, out);
}

// round 2
// speedup vs baseline: 1.5189x; 1.5189x over previous
#include <cuda_runtime.h>
#include <math.h>

#define Bn   2
#define Sn   2048
#define En   512
#define Hn   8
#define DHn  64
#define HIDn 2048
#define OUTn 6
#define Wn   5
#define SKn  2044          // S - W + 1
#define BSn  (Bn*Sn)       // 4096
#define NBH  (Bn*Hn)       // 16
#define NCHUNK 128

// ---------------- scratch (static device globals; no runtime alloc) ----------
__device__ float g_x [BSn*En];                    // current activations [B*S, E]
__device__ float g_x2[BSn*En];                    // temp (attn out / ffn out)
__device__ float g_q [NBH*Sn*DHn];                // [bh, s, dh]
__device__ float g_k [NBH*Sn*DHn];
__device__ float g_v [NBH*Sn*DHn];
__device__ float g_vs[NBH*SKn*DHn];               // window-summed V
__device__ float g_qk[(size_t)NBH*Sn*Sn];         // full QK^T   (268 MB)
__device__ float g_a [(size_t)NBH*Sn*Sn];         // softmax(A)  (268 MB, ld=Sn)
__device__ float g_h [BSn*HIDn];                  // ffn hidden
__device__ float g_part[Bn*NCHUNK*OUTn];          // final-gemm partials

// ---------------- embedding + positional encoding ----------------------------
__global__ void embed_kernel(const int* __restrict__ inputs,
                             const float* __restrict__ emb)
{
    int row = blockIdx.x;                 // b*S + s
    int s   = row % Sn;
    int tok = inputs[row];
    const float coef = -9.210340371976184f / (float)En;   // -ln(10000)/E
    for (int e = threadIdx.x; e < En; e += blockDim.x) {
        float freq = expf((float)(e & ~1) * coef);
        float ang  = (float)s * freq;
        float pe   = (e & 1) ? cosf(ang) : sinf(ang);
        g_x[(size_t)row*En + e] = emb[(size_t)tok*En + e] + pe;
    }
}

// =============================================================================
// 128x128 SGEMM core, 256 threads, 8x8 micro-tile, double-buffered smem.
// A row-major [M,K]; B row-major [K,N].  As stored transposed [k][m] (pad 132).
// =============================================================================

#define FMA8x8(acc, av, bv)                         \
    _Pragma("unroll")                               \
    for (int i_ = 0; i_ < 8; i_++)                  \
        _Pragma("unroll")                           \
        for (int j_ = 0; j_ < 8; j_++)              \
            acc[i_][j_] += av[i_] * bv[j_];

// ---------------- fused QKV: x[4096,512] @ {q_w,k_w,v_w}[512,512] -------------
struct QKVArgs {
    const float* W[3];
    const float* bias[3];
    float* out[3];
};

__global__ void __launch_bounds__(256, 2)
sgemm_qkv(const float* __restrict__ A, QKVArgs args)
{
    const int K = 512, N = 512;
    __shared__ float As[2][8][132];
    __shared__ float Bs[2][8][128];
    int z = blockIdx.z;
    const float* __restrict__ B    = args.W[z];
    const float* __restrict__ bias = args.bias[z];
    float* __restrict__ Cq         = args.out[z];

    int t  = threadIdx.x;
    int m0 = blockIdx.y * 128, n0 = blockIdx.x * 128;
    int ar = t >> 1, ac = (t & 1) * 4;
    int bk = t >> 5, bn = (t & 31) * 4;
    int tx = t & 15, ty = t >> 4;

    const float* Aptr = A + (size_t)(m0 + ar) * K + ac;
    const float* Bptr = B + (size_t)bk * N + n0 + bn;

    float4 ra = *(const float4*)Aptr;
    float4 rb = *(const float4*)Bptr;
    float acc[8][8] = {};
    const int nk = K / 8;

    #pragma unroll 1
    for (int ks = 0; ks < nk; ks++) {
        int buf = ks & 1;
        As[buf][ac+0][ar] = ra.x;
        As[buf][ac+1][ar] = ra.y;
        As[buf][ac+2][ar] = ra.z;
        As[buf][ac+3][ar] = ra.w;
        *(float4*)&Bs[buf][bk][bn] = rb;
        __syncthreads();
        if (ks + 1 < nk) {
            ra = *(const float4*)(Aptr + (ks+1)*8);
            rb = *(const float4*)(Bptr + (size_t)(ks+1)*8*N);
        }
        #pragma unroll
        for (int k = 0; k < 8; k++) {
            float4 a0 = *(const float4*)&As[buf][k][ty*4];
            float4 a1 = *(const float4*)&As[buf][k][64 + ty*4];
            float4 b0 = *(const float4*)&Bs[buf][k][tx*4];
            float4 b1 = *(const float4*)&Bs[buf][k][64 + tx*4];
            float av[8] = {a0.x,a0.y,a0.z,a0.w,a1.x,a1.y,a1.z,a1.w};
            float bv[8] = {b0.x,b0.y,b0.z,b0.w,b1.x,b1.y,b1.z,b1.w};
            FMA8x8(acc, av, bv);
        }
        __syncthreads();
    }

    #pragma unroll
    for (int ig = 0; ig < 2; ig++)
    #pragma unroll
    for (int i = 0; i < 4; i++) {
        int r = m0 + ig*64 + ty*4 + i;
        int bq = r >> 11, s = r & 2047;
        #pragma unroll
        for (int jg = 0; jg < 2; jg++) {
            int c = n0 + jg*64 + tx*4;
            int h = c >> 6, d = c & 63;
            float4 o;
            o.x = acc[ig*4+i][jg*4+0] + bias[c+0];
            o.y = acc[ig*4+i][jg*4+1] + bias[c+1];
            o.z = acc[ig*4+i][jg*4+2] + bias[c+2];
            o.w = acc[ig*4+i][jg*4+3] + bias[c+3];
            *(float4*)&Cq[(((size_t)(bq*Hn + h))*Sn + s)*DHn + d] = o;
        }
    }
}

// ---------------- FFN gemm: mode 1 = bias+relu, mode 2 = bias+residual --------
__global__ void __launch_bounds__(256, 2)
sgemm_ffn(const float* __restrict__ A, const float* __restrict__ B,
          float* __restrict__ C, const float* __restrict__ bias,
          const float* __restrict__ res, int K, int N, int mode)
{
    __shared__ float As[2][8][132];
    __shared__ float Bs[2][8][128];
    int t  = threadIdx.x;
    int m0 = blockIdx.y * 128, n0 = blockIdx.x * 128;
    int ar = t >> 1, ac = (t & 1) * 4;
    int bk = t >> 5, bn = (t & 31) * 4;
    int tx = t & 15, ty = t >> 4;

    const float* Aptr = A + (size_t)(m0 + ar) * K + ac;
    const float* Bptr = B + (size_t)bk * N + n0 + bn;

    float4 ra = *(const float4*)Aptr;
    float4 rb = *(const float4*)Bptr;
    float acc[8][8] = {};
    const int nk = K / 8;

    #pragma unroll 1
    for (int ks = 0; ks < nk; ks++) {
        int buf = ks & 1;
        As[buf][ac+0][ar] = ra.x;
        As[buf][ac+1][ar] = ra.y;
        As[buf][ac+2][ar] = ra.z;
        As[buf][ac+3][ar] = ra.w;
        *(float4*)&Bs[buf][bk][bn] = rb;
        __syncthreads();
        if (ks + 1 < nk) {
            ra = *(const float4*)(Aptr + (ks+1)*8);
            rb = *(const float4*)(Bptr + (size_t)(ks+1)*8*N);
        }
        #pragma unroll
        for (int k = 0; k < 8; k++) {
            float4 a0 = *(const float4*)&As[buf][k][ty*4];
            float4 a1 = *(const float4*)&As[buf][k][64 + ty*4];
            float4 b0 = *(const float4*)&Bs[buf][k][tx*4];
            float4 b1 = *(const float4*)&Bs[buf][k][64 + tx*4];
            float av[8] = {a0.x,a0.y,a0.z,a0.w,a1.x,a1.y,a1.z,a1.w};
            float bv[8] = {b0.x,b0.y,b0.z,b0.w,b1.x,b1.y,b1.z,b1.w};
            FMA8x8(acc, av, bv);
        }
        __syncthreads();
    }

    #pragma unroll
    for (int ig = 0; ig < 2; ig++)
    #pragma unroll
    for (int i = 0; i < 4; i++) {
        int r = m0 + ig*64 + ty*4 + i;
        #pragma unroll
        for (int jg = 0; jg < 2; jg++) {
            int c = n0 + jg*64 + tx*4;
            float4 o;
            o.x = acc[ig*4+i][jg*4+0] + bias[c+0];
            o.y = acc[ig*4+i][jg*4+1] + bias[c+1];
            o.z = acc[ig*4+i][jg*4+2] + bias[c+2];
            o.w = acc[ig*4+i][jg*4+3] + bias[c+3];
            if (mode == 1) {
                o.x = fmaxf(o.x, 0.f); o.y = fmaxf(o.y, 0.f);
                o.z = fmaxf(o.z, 0.f); o.w = fmaxf(o.w, 0.f);
            } else {
                const float4 rr = *(const float4*)&res[(size_t)r*N + c];
                o.x += rr.x; o.y += rr.y; o.z += rr.z; o.w += rr.w;
            }
            *(float4*)&C[(size_t)r*N + c] = o;
        }
    }
}

// ---------------- batched QK^T (NT), 128x128 tile, K=64 ----------------------
__global__ void __launch_bounds__(256, 2)
sgemm_qkT()
{
    __shared__ float As[2][8][132];
    __shared__ float Bs[2][8][132];
    int z  = blockIdx.z;
    const float* __restrict__ Q  = g_q + (size_t)z * Sn * DHn;
    const float* __restrict__ Km = g_k + (size_t)z * Sn * DHn;
    float* __restrict__ C        = g_qk + (size_t)z * Sn * Sn;

    int t  = threadIdx.x;
    int q0 = blockIdx.y * 128, t0 = blockIdx.x * 128;
    int ar = t >> 1, ac = (t & 1) * 4;
    int tx = t & 15, ty = t >> 4;

    const float* Aptr = Q  + (size_t)(q0 + ar) * DHn + ac;
    const float* Bptr = Km + (size_t)(t0 + ar) * DHn + ac;

    float4 ra = *(const float4*)Aptr;
    float4 rb = *(const float4*)Bptr;
    float acc[8][8] = {};
    const int nk = DHn / 8;   // 8

    #pragma unroll 1
    for (int ks = 0; ks < nk; ks++) {
        int buf = ks & 1;
        As[buf][ac+0][ar] = ra.x;  As[buf][ac+1][ar] = ra.y;
        As[buf][ac+2][ar] = ra.z;  As[buf][ac+3][ar] = ra.w;
        Bs[buf][ac+0][ar] = rb.x;  Bs[buf][ac+1][ar] = rb.y;
        Bs[buf][ac+2][ar] = rb.z;  Bs[buf][ac+3][ar] = rb.w;
        __syncthreads();
        if (ks + 1 < nk) {
            ra = *(const float4*)(Aptr + (ks+1)*8);
            rb = *(const float4*)(Bptr + (ks+1)*8);
        }
        #pragma unroll
        for (int k = 0; k < 8; k++) {
            float4 a0 = *(const float4*)&As[buf][k][ty*4];
            float4 a1 = *(const float4*)&As[buf][k][64 + ty*4];
            float4 b0 = *(const float4*)&Bs[buf][k][tx*4];
            float4 b1 = *(const float4*)&Bs[buf][k][64 + tx*4];
            float av[8] = {a0.x,a0.y,a0.z,a0.w,a1.x,a1.y,a1.z,a1.w};
            float bv[8] = {b0.x,b0.y,b0.z,b0.w,b1.x,b1.y,b1.z,b1.w};
            FMA8x8(acc, av, bv);
        }
        __syncthreads();
    }

    #pragma unroll
    for (int ig = 0; ig < 2; ig++)
    #pragma unroll
    for (int i = 0; i < 4; i++) {
        int r = q0 + ig*64 + ty*4 + i;
        #pragma unroll
        for (int jg = 0; jg < 2; jg++) {
            int c = t0 + jg*64 + tx*4;
            float4 o;
            o.x = acc[ig*4+i][jg*4+0];
            o.y = acc[ig*4+i][jg*4+1];
            o.z = acc[ig*4+i][jg*4+2];
            o.w = acc[ig*4+i][jg*4+3];
            *(float4*)&C[(size_t)r*Sn + c] = o;
        }
    }
}

// ---------------- A @ Vsum, 128x64 tile, scatter to x2 ------------------------
__global__ void __launch_bounds__(256, 2)
sgemm_av()
{
    __shared__ float As[2][8][132];
    __shared__ float Vs[2][8][68];
    int z  = blockIdx.y;              // bh
    int q0 = blockIdx.x * 128;
    const float* __restrict__ A = g_a  + (size_t)z * Sn * Sn;
    const float* __restrict__ V = g_vs + (size_t)z * SKn * DHn;

    int t  = threadIdx.x;
    int ar = t >> 1, ac = (t & 1) * 4;
    int tx = t & 15, ty = t >> 4;

    const float* Aptr = A + (size_t)(q0 + ar) * Sn + ac;
    int vk = t >> 4, vd = (t & 15) * 4;   // threads 0..127 load V

    float4 ra = *(const float4*)Aptr;
    float4 rb = make_float4(0.f,0.f,0.f,0.f);
    if (t < 128 && vk < SKn)
        rb = *(const float4*)&V[(size_t)vk * DHn + vd];

    float acc[8][4] = {};
    const int nk = Sn / 8;   // 256 (padded; A cols 2044..2047 are 0, V padded 0)

    #pragma unroll 1
    for (int ks = 0; ks < nk; ks++) {
        int buf = ks & 1;
        As[buf][ac+0][ar] = ra.x;  As[buf][ac+1][ar] = ra.y;
        As[buf][ac+2][ar] = ra.z;  As[buf][ac+3][ar] = ra.w;
        if (t < 128) *(float4*)&Vs[buf][vk][vd] = rb;
        __syncthreads();
        if (ks + 1 < nk) {
            ra = *(const float4*)(Aptr + (ks+1)*8);
            int row = (ks+1)*8 + vk;
            rb = make_float4(0.f,0.f,0.f,0.f);
            if (t < 128 && row < SKn)
                rb = *(const float4*)&V[(size_t)row * DHn + vd];
        }
        #pragma unroll
        for (int k = 0; k < 8; k++) {
            float4 a0 = *(const float4*)&As[buf][k][ty*4];
            float4 a1 = *(const float4*)&As[buf][k][64 + ty*4];
            float4 b0 = *(const float4*)&Vs[buf][k][tx*4];
            float av[8] = {a0.x,a0.y,a0.z,a0.w,a1.x,a1.y,a1.z,a1.w};
            float bv[4] = {b0.x,b0.y,b0.z,b0.w};
            #pragma unroll
            for (int i = 0; i < 8; i++)
                #pragma unroll
                for (int j = 0; j < 4; j++)
                    acc[i][j] += av[i] * bv[j];
        }
        __syncthreads();
    }

    int b = z >> 3, h = z & 7;
    #pragma unroll
    for (int ig = 0; ig < 2; ig++)
    #pragma unroll
    for (int i = 0; i < 4; i++) {
        int q = q0 + ig*64 + ty*4 + i;
        float4 o;
        o.x = acc[ig*4+i][0]; o.y = acc[ig*4+i][1];
        o.z = acc[ig*4+i][2]; o.w = acc[ig*4+i][3];
        *(float4*)&g_x2[(((size_t)b*Sn) + q)*En + h*DHn + tx*4] = o;
    }
}

// ---------------- window-sum (5 shifted diagonals) + softmax -----------------
__global__ void win_softmax()
{
    int q  = blockIdx.x;
    int bh = blockIdx.y;
    const float* qk = g_qk + (size_t)bh * Sn * Sn;
    float* arow     = g_a  + (size_t)bh * Sn * Sn + (size_t)q * Sn;
    __shared__ float row[SKn];
    __shared__ float red[256];
    int tid = threadIdx.x;

    float lmax = -1e30f;
    for (int t = tid; t < SKn; t += 256) {
        float s = 0.f;
        #pragma unroll
        for (int j = 0; j < Wn; j++) {
            int qi = q + j - 2;
            if (qi >= 0 && qi < Sn) s += qk[(size_t)qi*Sn + (t + j)];
        }
        s *= 0.125f;      // DH^-0.5
        row[t] = s;
        lmax = fmaxf(lmax, s);
    }
    red[tid] = lmax; __syncthreads();
    for (int o = 128; o > 0; o >>= 1) {
        if (tid < o) red[tid] = fmaxf(red[tid], red[tid+o]);
        __syncthreads();
    }
    float m = red[0]; __syncthreads();

    float lsum = 0.f;
    for (int t = tid; t < SKn; t += 256) {
        float e = __expf(row[t] - m);
        row[t] = e;
        lsum += e;
    }
    red[tid] = lsum; __syncthreads();
    for (int o = 128; o > 0; o >>= 1) {
        if (tid < o) red[tid] += red[tid+o];
        __syncthreads();
    }
    float inv = 1.f / red[0];
    for (int t = tid; t < SKn; t += 256) arow[t] = row[t] * inv;
}

// ---------------- V window pre-sum -------------------------------------------
__global__ void vsum_kernel()
{
    int idx = blockIdx.x * 256 + threadIdx.x;
    if (idx >= NBH*SKn*DHn) return;
    int d  = idx % DHn;
    int t  = (idx / DHn) % SKn;
    int bh = idx / (DHn*SKn);
    const float* v = g_v + (size_t)bh * Sn * DHn;
    float s = 0.f;
    #pragma unroll
    for (int j = 0; j < Wn; j++) s += v[(size_t)(t + j)*DHn + d];
    g_vs[idx] = s;
}

// ---------------- layernorm (E = 512) ----------------------------------------
__global__ void layernorm_kernel(const float* __restrict__ in,
                                 float* __restrict__ out,
                                 const float* __restrict__ w,
                                 const float* __restrict__ b)
{
    int row = blockIdx.x;
    int tid = threadIdx.x;
    const float* xr = in + (size_t)row * En;
    float v0 = xr[tid], v1 = xr[tid + 256];
    __shared__ float s1[256], s2[256];
    s1[tid] = v0 + v1;
    s2[tid] = v0*v0 + v1*v1;
    __syncthreads();
    for (int o = 128; o > 0; o >>= 1) {
        if (tid < o) { s1[tid] += s1[tid+o]; s2[tid] += s2[tid+o]; }
        __syncthreads();
    }
    float mean = s1[0] * (1.f/En);
    float var  = s2[0] * (1.f/En) - mean*mean;
    float rstd = rsqrtf(var + 1e-5f);
    float* orow = out + (size_t)row * En;
    orow[tid]       = (v0 - mean) * rstd * w[tid]       + b[tid];
    orow[tid + 256] = (v1 - mean) * rstd * w[tid + 256] + b[tid + 256];
}

// ---------------- final projection x[B, S*E] @ out_w[S*E, 6] -----------------
__global__ void out_stage1(const float* __restrict__ out_w)
{
    int b = blockIdx.y, chunk = blockIdx.x;
    int tid = threadIdx.x;
    const int CH = Sn*En / NCHUNK;               // 8192
    const float* xr = g_x + (size_t)b*Sn*En + (size_t)chunk*CH;
    const float* wr = out_w + (size_t)chunk*CH*OUTn;
    float acc[OUTn] = {};
    for (int i = tid; i < CH; i += 256) {
        float xv = xr[i];
        #pragma unroll
        for (int o = 0; o < OUTn; o++) acc[o] += xv * wr[(size_t)i*OUTn + o];
    }
    __shared__ float red[OUTn*256];
    #pragma unroll
    for (int o = 0; o < OUTn; o++) red[o*256 + tid] = acc[o];
    __syncthreads();
    for (int st = 128; st > 0; st >>= 1) {
        if (tid < st)
            #pragma unroll
            for (int o = 0; o < OUTn; o++)
                red[o*256 + tid] += red[o*256 + tid + st];
        __syncthreads();
    }
    if (tid < OUTn) g_part[(b*NCHUNK + chunk)*OUTn + tid] = red[tid*256];
}

__global__ void out_stage2(const float* __restrict__ out_b,
                           float* __restrict__ out)
{
    int tid = threadIdx.x;
    if (tid < Bn*OUTn) {
        int b = tid / OUTn, o = tid % OUTn;
        float s = out_b[o];
        for (int c = 0; c < NCHUNK; c++)
            s += g_part[(b*NCHUNK + c)*OUTn + o];
        out[tid] = s;
    }
}

// ---------------- driver ------------------------------------------------------
extern "C" void kernel_launch(void* const* d_in, const int* in_sizes, int n_in,
                              void* d_out, int out_size)
{
    const int*   inputs = (const int*)  d_in[0];
    const float* emb    = (const float*)d_in[1];
    const float* ln_w   = (const float*)d_in[2];
    const float* ln_b   = (const float*)d_in[3];
    const float* q_w    = (const float*)d_in[4];
    const float* q_b    = (const float*)d_in[5];
    const float* k_w    = (const float*)d_in[6];
    const float* k_b    = (const float*)d_in[7];
    const float* v_w    = (const float*)d_in[8];
    const float* v_b    = (const float*)d_in[9];
    const float* fc1_w  = (const float*)d_in[10];
    const float* fc1_b  = (const float*)d_in[11];
    const float* fc2_w  = (const float*)d_in[12];
    const float* fc2_b  = (const float*)d_in[13];
    const float* out_w  = (const float*)d_in[14];
    const float* out_b  = (const float*)d_in[15];
    float* out = (float*)d_out;

    float *px, *px2, *pq, *pk, *pv, *ph;
    cudaGetSymbolAddress((void**)&px,  g_x);
    cudaGetSymbolAddress((void**)&px2, g_x2);
    cudaGetSymbolAddress((void**)&pq,  g_q);
    cudaGetSymbolAddress((void**)&pk,  g_k);
    cudaGetSymbolAddress((void**)&pv,  g_v);
    cudaGetSymbolAddress((void**)&ph,  g_h);

    embed_kernel<<<BSn, 256>>>(inputs, emb);

    QKVArgs qa;
    qa.W[0] = q_w;  qa.W[1] = k_w;  qa.W[2] = v_w;
    qa.bias[0] = q_b; qa.bias[1] = k_b; qa.bias[2] = v_b;
    qa.out[0] = pq; qa.out[1] = pk; qa.out[2] = pv;

    for (int l = 0; l < 6; l++) {
        sgemm_qkv<<<dim3(En/128, BSn/128, 3), 256>>>(px, qa);

        sgemm_qkT<<<dim3(Sn/128, Sn/128, NBH), 256>>>();
        win_softmax<<<dim3(Sn, NBH), 256>>>();
        vsum_kernel<<<(NBH*SKn*DHn + 255)/256, 256>>>();
        sgemm_av<<<dim3(Sn/128, NBH), 256>>>();

        layernorm_kernel<<<BSn, 256>>>(px2, px, ln_w, ln_b);

        sgemm_ffn<<<dim3(HIDn/128, BSn/128), 256>>>(px, fc1_w, ph, fc1_b,
                                                    nullptr, En, HIDn, 1);
        sgemm_ffn<<<dim3(En/128, BSn/128), 256>>>(ph, fc2_w, px2, fc2_b,
                                                  px, HIDn, En, 2);

        layernorm_kernel<<<BSn, 256>>>(px2, px, ln_w, ln_b);
    }

    out_stage1<<<dim3(NCHUNK, Bn), 256>>>(out_w);
    out_stage2<<<1, 32>>>(out_b, out);
}

// round 5
// speedup vs baseline: 1.6621x; 1.0942x over previous
#include <cuda_runtime.h>
#include <math.h>

#define Bn   2
#define Sn   2048
#define En   512
#define Hn   8
#define DHn  64
#define HIDn 2048
#define OUTn 6
#define Wn   5
#define SKn  2044          // S - W + 1
#define BSn  (Bn*Sn)       // 4096
#define NBH  (Bn*Hn)       // 16
#define NCHUNK 128
#define QB   124           // score tile (queries & keys per chunk)
#define NQB  17            // ceil(2048/124)
#define NTC  17            // ceil(2044/124)

// ---------------- scratch (static device globals; no runtime alloc) ----------
__device__ float g_x [BSn*En];
__device__ float g_x2[BSn*En];
__device__ float g_q [NBH*Sn*DHn];
__device__ float g_k [NBH*Sn*DHn];
__device__ float g_v [NBH*Sn*DHn];
__device__ float g_vs[NBH*SKn*DHn];
__device__ float g_h [BSn*HIDn];
__device__ float g_part[Bn*NCHUNK*OUTn];

// ---------------- embedding + positional encoding ----------------------------
__global__ void embed_kernel(const int* __restrict__ inputs,
                             const float* __restrict__ emb)
{
    int row = blockIdx.x;
    int s   = row % Sn;
    int tok = inputs[row];
    const float coef = -9.210340371976184f / (float)En;
    for (int e = threadIdx.x; e < En; e += blockDim.x) {
        float freq = expf((float)(e & ~1) * coef);
        float ang  = (float)s * freq;
        float pe   = (e & 1) ? cosf(ang) : sinf(ang);
        g_x[(size_t)row*En + e] = emb[(size_t)tok*En + e] + pe;
    }
}

#define FMA8x8(acc, av, bv)                         \
    _Pragma("unroll")                               \
    for (int i_ = 0; i_ < 8; i_++)                  \
        _Pragma("unroll")                           \
        for (int j_ = 0; j_ < 8; j_++)              \
            acc[i_][j_] += av[i_] * bv[j_];

// ---------------- fused QKV gemm ----------------------------------------------
struct QKVArgs {
    const float* W[3];
    const float* bias[3];
    float* out[3];
};

__global__ void __launch_bounds__(256, 2)
sgemm_qkv(const float* __restrict__ A, QKVArgs args)
{
    const int K = 512, N = 512;
    __shared__ float As[2][8][132];
    __shared__ float Bs[2][8][128];
    int z = blockIdx.z;
    const float* __restrict__ B    = args.W[z];
    const float* __restrict__ bias = args.bias[z];
    float* __restrict__ Cq         = args.out[z];

    int t  = threadIdx.x;
    int m0 = blockIdx.y * 128, n0 = blockIdx.x * 128;
    int ar = t >> 1, ac = (t & 1) * 4;
    int bk = t >> 5, bn = (t & 31) * 4;
    int tx = t & 15, ty = t >> 4;

    const float* Aptr = A + (size_t)(m0 + ar) * K + ac;
    const float* Bptr = B + (size_t)bk * N + n0 + bn;

    float4 ra = *(const float4*)Aptr;
    float4 rb = *(const float4*)Bptr;
    float acc[8][8] = {};
    const int nk = K / 8;

    #pragma unroll 1
    for (int ks = 0; ks < nk; ks++) {
        int buf = ks & 1;
        As[buf][ac+0][ar] = ra.x;
        As[buf][ac+1][ar] = ra.y;
        As[buf][ac+2][ar] = ra.z;
        As[buf][ac+3][ar] = ra.w;
        *(float4*)&Bs[buf][bk][bn] = rb;
        __syncthreads();
        if (ks + 1 < nk) {
            ra = *(const float4*)(Aptr + (ks+1)*8);
            rb = *(const float4*)(Bptr + (size_t)(ks+1)*8*N);
        }
        #pragma unroll
        for (int k = 0; k < 8; k++) {
            float4 a0 = *(const float4*)&As[buf][k][ty*4];
            float4 a1 = *(const float4*)&As[buf][k][64 + ty*4];
            float4 b0 = *(const float4*)&Bs[buf][k][tx*4];
            float4 b1 = *(const float4*)&Bs[buf][k][64 + tx*4];
            float av[8] = {a0.x,a0.y,a0.z,a0.w,a1.x,a1.y,a1.z,a1.w};
            float bv[8] = {b0.x,b0.y,b0.z,b0.w,b1.x,b1.y,b1.z,b1.w};
            FMA8x8(acc, av, bv);
        }
        __syncthreads();
    }

    #pragma unroll
    for (int ig = 0; ig < 2; ig++)
    #pragma unroll
    for (int i = 0; i < 4; i++) {
        int r = m0 + ig*64 + ty*4 + i;
        int bq = r >> 11, s = r & 2047;
        #pragma unroll
        for (int jg = 0; jg < 2; jg++) {
            int c = n0 + jg*64 + tx*4;
            int h = c >> 6, d = c & 63;
            float4 o;
            o.x = acc[ig*4+i][jg*4+0] + bias[c+0];
            o.y = acc[ig*4+i][jg*4+1] + bias[c+1];
            o.z = acc[ig*4+i][jg*4+2] + bias[c+2];
            o.w = acc[ig*4+i][jg*4+3] + bias[c+3];
            *(float4*)&Cq[(((size_t)(bq*Hn + h))*Sn + s)*DHn + d] = o;
        }
    }
}

// ---------------- FFN gemm: mode 1 = bias+relu, mode 2 = bias+residual --------
__global__ void __launch_bounds__(256, 2)
sgemm_ffn(const float* __restrict__ A, const float* __restrict__ B,
          float* __restrict__ C, const float* __restrict__ bias,
          const float* __restrict__ res, int K, int N, int mode)
{
    __shared__ float As[2][8][132];
    __shared__ float Bs[2][8][128];
    int t  = threadIdx.x;
    int m0 = blockIdx.y * 128, n0 = blockIdx.x * 128;
    int ar = t >> 1, ac = (t & 1) * 4;
    int bk = t >> 5, bn = (t & 31) * 4;
    int tx = t & 15, ty = t >> 4;

    const float* Aptr = A + (size_t)(m0 + ar) * K + ac;
    const float* Bptr = B + (size_t)bk * N + n0 + bn;

    float4 ra = *(const float4*)Aptr;
    float4 rb = *(const float4*)Bptr;
    float acc[8][8] = {};
    const int nk = K / 8;

    #pragma unroll 1
    for (int ks = 0; ks < nk; ks++) {
        int buf = ks & 1;
        As[buf][ac+0][ar] = ra.x;
        As[buf][ac+1][ar] = ra.y;
        As[buf][ac+2][ar] = ra.z;
        As[buf][ac+3][ar] = ra.w;
        *(float4*)&Bs[buf][bk][bn] = rb;
        __syncthreads();
        if (ks + 1 < nk) {
            ra = *(const float4*)(Aptr + (ks+1)*8);
            rb = *(const float4*)(Bptr + (size_t)(ks+1)*8*N);
        }
        #pragma unroll
        for (int k = 0; k < 8; k++) {
            float4 a0 = *(const float4*)&As[buf][k][ty*4];
            float4 a1 = *(const float4*)&As[buf][k][64 + ty*4];
            float4 b0 = *(const float4*)&Bs[buf][k][tx*4];
            float4 b1 = *(const float4*)&Bs[buf][k][64 + tx*4];
            float av[8] = {a0.x,a0.y,a0.z,a0.w,a1.x,a1.y,a1.z,a1.w};
            float bv[8] = {b0.x,b0.y,b0.z,b0.w,b1.x,b1.y,b1.z,b1.w};
            FMA8x8(acc, av, bv);
        }
        __syncthreads();
    }

    #pragma unroll
    for (int ig = 0; ig < 2; ig++)
    #pragma unroll
    for (int i = 0; i < 4; i++) {
        int r = m0 + ig*64 + ty*4 + i;
        #pragma unroll
        for (int jg = 0; jg < 2; jg++) {
            int c = n0 + jg*64 + tx*4;
            float4 o;
            o.x = acc[ig*4+i][jg*4+0] + bias[c+0];
            o.y = acc[ig*4+i][jg*4+1] + bias[c+1];
            o.z = acc[ig*4+i][jg*4+2] + bias[c+2];
            o.w = acc[ig*4+i][jg*4+3] + bias[c+3];
            if (mode == 1) {
                o.x = fmaxf(o.x, 0.f); o.y = fmaxf(o.y, 0.f);
                o.z = fmaxf(o.z, 0.f); o.w = fmaxf(o.w, 0.f);
            } else {
                const float4 rr = *(const float4*)&res[(size_t)r*N + c];
                o.x += rr.x; o.y += rr.y; o.z += rr.z; o.w += rr.w;
            }
            *(float4*)&C[(size_t)r*N + c] = o;
        }
    }
}

// ---------------- V window pre-sum -------------------------------------------
__global__ void vsum_kernel()
{
    int idx = blockIdx.x * 256 + threadIdx.x;
    if (idx >= NBH*SKn*DHn) return;
    int d  = idx % DHn;
    int t  = (idx / DHn) % SKn;
    int bh = idx / (DHn*SKn);
    const float* v = g_v + (size_t)bh * Sn * DHn;
    float s = 0.f;
    #pragma unroll
    for (int j = 0; j < Wn; j++) s += v[(size_t)(t + j)*DHn + d];
    g_vs[idx] = s;
}

// =============================================================================
// Fused attention: QK^T halo tile + 5-diag window sum + online softmax + P@Vsum
// One block per (q-block of 124, bh). 256 threads. Never materializes scores.
// =============================================================================
__device__ __forceinline__ int rowmap(int ty, int i) {
    return (i < 4) ? (ty*4 + i) : (64 + ty*4 + (i - 4));
}

#define SM_QS 0
#define SM_KS (64*132)
#define SM_VS (2*64*132)
#define SM_TT (2*64*132 + QB*68)
#define SM_FLOATS (2*64*132 + QB*68 + 132*132)

__global__ void __launch_bounds__(256, 1)
attn_fused()
{
    extern __shared__ float sm[];
    float* Qs = sm + SM_QS;      // [64][132] k-major, 128 halo rows
    float* Ks = sm + SM_KS;      // [64][132] k-major, 128 halo rows
    float* Vs = sm + SM_VS;      // [QB][68]
    float* Tt = sm + SM_TT;      // [132][132] raw QK tile; reused as P[q][t]

    int bh = blockIdx.y;
    int q0 = blockIdx.x * QB;
    const float* __restrict__ Q = g_q  + (size_t)bh*Sn*DHn;
    const float* __restrict__ K = g_k  + (size_t)bh*Sn*DHn;
    const float* __restrict__ V = g_vs + (size_t)bh*SKn*DHn;

    int t  = threadIdx.x;
    int tx = t & 15, ty = t >> 4;
    int lr = t >> 1, lc4 = (t & 1) * 4;

    // ---- load Q halo: global rows q0-2 .. q0+125, zero-padded ----
    {
        int gq = q0 - 2 + lr;
        bool ok = (gq >= 0 && gq < Sn);
        const float* qp = Q + (size_t)(ok ? gq : 0)*DHn;
        #pragma unroll
        for (int p = 0; p < 8; p++) {
            int c = p*8 + lc4;
            float4 v = make_float4(0.f,0.f,0.f,0.f);
            if (ok) v = *(const float4*)(qp + c);
            Qs[(c+0)*132 + lr] = v.x;
            Qs[(c+1)*132 + lr] = v.y;
            Qs[(c+2)*132 + lr] = v.z;
            Qs[(c+3)*132 + lr] = v.w;
        }
    }

    float m[8], l[8], acc[8][4];
    #pragma unroll
    for (int i = 0; i < 8; i++) {
        m[i] = -1e30f; l[i] = 0.f;
        #pragma unroll
        for (int j = 0; j < 4; j++) acc[i][j] = 0.f;
    }

    #pragma unroll 1
    for (int tc = 0; tc < NTC; tc++) {
        int t0 = tc * QB;
        __syncthreads();   // prev iter's Ks/Vs/Tt consumers done

        // ---- load K halo rows t0 .. t0+127 (zero-pad past Sn) ----
        {
            int gk = t0 + lr;
            bool ok = (gk < Sn);
            const float* kp = K + (size_t)(ok ? gk : 0)*DHn;
            #pragma unroll
            for (int p = 0; p < 8; p++) {
                int c = p*8 + lc4;
                float4 v = make_float4(0.f,0.f,0.f,0.f);
                if (ok) v = *(const float4*)(kp + c);
                Ks[(c+0)*132 + lr] = v.x;
                Ks[(c+1)*132 + lr] = v.y;
                Ks[(c+2)*132 + lr] = v.z;
                Ks[(c+3)*132 + lr] = v.w;
            }
        }
        // ---- load Vsum rows t0 .. t0+123 (zero-pad past SKn) ----
        if (lr < QB) {
            int gv = t0 + lr;
            bool ok = (gv < SKn);
            const float* vp = V + (size_t)(ok ? gv : 0)*DHn;
            #pragma unroll
            for (int p = 0; p < 8; p++) {
                int c = p*8 + lc4;
                float4 v = make_float4(0.f,0.f,0.f,0.f);
                if (ok) v = *(const float4*)(vp + c);
                *(float4*)&Vs[lr*68 + c] = v;
            }
        }
        __syncthreads();

        // ---- raw QK halo tile: T[128][128] in registers ----
        float tacc[8][8] = {};
        #pragma unroll 8
        for (int k = 0; k < 64; k++) {
            float4 a0 = *(const float4*)&Qs[k*132 + ty*4];
            float4 a1 = *(const float4*)&Qs[k*132 + 64 + ty*4];
            float4 b0 = *(const float4*)&Ks[k*132 + tx*4];
            float4 b1 = *(const float4*)&Ks[k*132 + 64 + tx*4];
            float av[8] = {a0.x,a0.y,a0.z,a0.w,a1.x,a1.y,a1.z,a1.w};
            float bv[8] = {b0.x,b0.y,b0.z,b0.w,b1.x,b1.y,b1.z,b1.w};
            FMA8x8(tacc, av, bv);
        }
        // write T to smem
        #pragma unroll
        for (int i = 0; i < 8; i++) {
            int qh = rowmap(ty, i);
            #pragma unroll
            for (int jg = 0; jg < 2; jg++) {
                float4 o;
                o.x = tacc[i][jg*4+0]; o.y = tacc[i][jg*4+1];
                o.z = tacc[i][jg*4+2]; o.w = tacc[i][jg*4+3];
                *(float4*)&Tt[qh*132 + jg*64 + tx*4] = o;
            }
        }
        __syncthreads();

        // ---- window-sum + mask + online softmax ----
        float pv[8][8];
        #pragma unroll
        for (int i = 0; i < 8; i++) {
            int q = rowmap(ty, i);          // local q row
            float s8[8];
            #pragma unroll
            for (int jg = 0; jg < 2; jg++) {
                int cb = jg*64 + tx*4;
                float s4[4] = {0.f,0.f,0.f,0.f};
                if (q < QB) {
                    #pragma unroll
                    for (int w = 0; w < Wn; w++) {
                        const float* rp = &Tt[(q+w)*132 + cb];
                        float4 a = *(const float4*)rp;
                        float4 b = *(const float4*)(rp + 4);
                        float tv[8] = {a.x,a.y,a.z,a.w,b.x,b.y,b.z,b.w};
                        #pragma unroll
                        for (int j = 0; j < 4; j++) s4[j] += tv[w + j];
                    }
                }
                #pragma unroll
                for (int j = 0; j < 4; j++) {
                    int lt = cb + j;          // local key index in this tile
                    int gt = t0 + lt;         // global key index
                    // emit ONLY keys owned by this tile: lt < QB (tiles
                    // advance by QB; lt in [QB,128) belongs to next tile)
                    s8[jg*4+j] = (lt < QB && gt < SKn && q < QB)
                                 ? s4[j]*0.125f : -1e30f;
                }
            }
            // row max across 8 local + 16 tx lanes
            float r = s8[0];
            #pragma unroll
            for (int j = 1; j < 8; j++) r = fmaxf(r, s8[j]);
            #pragma unroll
            for (int o = 1; o < 16; o <<= 1)
                r = fmaxf(r, __shfl_xor_sync(0xffffffffu, r, o));
            float mn = fmaxf(m[i], r);
            float corr = __expf(m[i] - mn);
            float rs = 0.f;
            #pragma unroll
            for (int j = 0; j < 8; j++) {
                float e = __expf(s8[j] - mn);
                pv[i][j] = e;
                rs += e;
            }
            #pragma unroll
            for (int o = 1; o < 16; o <<= 1)
                rs += __shfl_xor_sync(0xffffffffu, rs, o);
            l[i] = l[i]*corr + rs;
            m[i] = mn;
            #pragma unroll
            for (int j = 0; j < 4; j++) acc[i][j] *= corr;
        }
        __syncthreads();   // everyone done reading Tt

        // ---- write P[q][t] into Tt buffer ----
        #pragma unroll
        for (int i = 0; i < 8; i++) {
            int q = rowmap(ty, i);
            #pragma unroll
            for (int jg = 0; jg < 2; jg++) {
                float4 o;
                o.x = pv[i][jg*4+0]; o.y = pv[i][jg*4+1];
                o.z = pv[i][jg*4+2]; o.w = pv[i][jg*4+3];
                *(float4*)&Tt[q*132 + jg*64 + tx*4] = o;
            }
        }
        __syncthreads();

        // ---- acc += P @ Vs  (contract t = 0..QB-1) ----
        #pragma unroll 4
        for (int k = 0; k < QB; k++) {
            float4 b = *(const float4*)&Vs[k*68 + tx*4];
            float bv[4] = {b.x, b.y, b.z, b.w};
            #pragma unroll
            for (int i = 0; i < 8; i++) {
                float a = Tt[rowmap(ty, i)*132 + k];
                #pragma unroll
                for (int j = 0; j < 4; j++) acc[i][j] += a * bv[j];
            }
        }
    }

    // ---- normalize + scatter to g_x2[b, q, h*64+d] ----
    int b = bh >> 3, h = bh & 7;
    #pragma unroll
    for (int i = 0; i < 8; i++) {
        int q = rowmap(ty, i);
        int gq = q0 + q;
        if (q < QB && gq < Sn) {
            float inv = 1.f / l[i];
            float4 o;
            o.x = acc[i][0]*inv; o.y = acc[i][1]*inv;
            o.z = acc[i][2]*inv; o.w = acc[i][3]*inv;
            *(float4*)&g_x2[((size_t)(b*Sn) + gq)*En + h*DHn + tx*4] = o;
        }
    }
}

// ---------------- layernorm (E = 512) ----------------------------------------
__global__ void layernorm_kernel(const float* __restrict__ in,
                                 float* __restrict__ out,
                                 const float* __restrict__ w,
                                 const float* __restrict__ b)
{
    int row = blockIdx.x;
    int tid = threadIdx.x;
    const float* xr = in + (size_t)row * En;
    float v0 = xr[tid], v1 = xr[tid + 256];
    __shared__ float s1[256], s2[256];
    s1[tid] = v0 + v1;
    s2[tid] = v0*v0 + v1*v1;
    __syncthreads();
    for (int o = 128; o > 0; o >>= 1) {
        if (tid < o) { s1[tid] += s1[tid+o]; s2[tid] += s2[tid+o]; }
        __syncthreads();
    }
    float mean = s1[0] * (1.f/En);
    float var  = s2[0] * (1.f/En) - mean*mean;
    float rstd = rsqrtf(var + 1e-5f);
    float* orow = out + (size_t)row * En;
    orow[tid]       = (v0 - mean) * rstd * w[tid]       + b[tid];
    orow[tid + 256] = (v1 - mean) * rstd * w[tid + 256] + b[tid + 256];
}

// ---------------- final projection x[B, S*E] @ out_w[S*E, 6] -----------------
__global__ void out_stage1(const float* __restrict__ out_w)
{
    int b = blockIdx.y, chunk = blockIdx.x;
    int tid = threadIdx.x;
    const int CH = Sn*En / NCHUNK;
    const float* xr = g_x + (size_t)b*Sn*En + (size_t)chunk*CH;
    const float* wr = out_w + (size_t)chunk*CH*OUTn;
    float acc[OUTn] = {};
    for (int i = tid; i < CH; i += 256) {
        float xv = xr[i];
        #pragma unroll
        for (int o = 0; o < OUTn; o++) acc[o] += xv * wr[(size_t)i*OUTn + o];
    }
    __shared__ float red[OUTn*256];
    #pragma unroll
    for (int o = 0; o < OUTn; o++) red[o*256 + tid] = acc[o];
    __syncthreads();
    for (int st = 128; st > 0; st >>= 1) {
        if (tid < st)
            #pragma unroll
            for (int o = 0; o < OUTn; o++)
                red[o*256 + tid] += red[o*256 + tid + st];
        __syncthreads();
    }
    if (tid < OUTn) g_part[(b*NCHUNK + chunk)*OUTn + tid] = red[tid*256];
}

__global__ void out_stage2(const float* __restrict__ out_b,
                           float* __restrict__ out)
{
    int tid = threadIdx.x;
    if (tid < Bn*OUTn) {
        int b = tid / OUTn, o = tid % OUTn;
        float s = out_b[o];
        for (int c = 0; c < NCHUNK; c++)
            s += g_part[(b*NCHUNK + c)*OUTn + o];
        out[tid] = s;
    }
}

// ---------------- driver ------------------------------------------------------
extern "C" void kernel_launch(void* const* d_in, const int* in_sizes, int n_in,
                              void* d_out, int out_size)
{
    const int*   inputs = (const int*)  d_in[0];
    const float* emb    = (const float*)d_in[1];
    const float* ln_w   = (const float*)d_in[2];
    const float* ln_b   = (const float*)d_in[3];
    const float* q_w    = (const float*)d_in[4];
    const float* q_b    = (const float*)d_in[5];
    const float* k_w    = (const float*)d_in[6];
    const float* k_b    = (const float*)d_in[7];
    const float* v_w    = (const float*)d_in[8];
    const float* v_b    = (const float*)d_in[9];
    const float* fc1_w  = (const float*)d_in[10];
    const float* fc1_b  = (const float*)d_in[11];
    const float* fc2_w  = (const float*)d_in[12];
    const float* fc2_b  = (const float*)d_in[13];
    const float* out_w  = (const float*)d_in[14];
    const float* out_b  = (const float*)d_in[15];
    float* out = (float*)d_out;

    float *px, *px2, *pq, *pk, *pv, *ph;
    cudaGetSymbolAddress((void**)&px,  g_x);
    cudaGetSymbolAddress((void**)&px2, g_x2);
    cudaGetSymbolAddress((void**)&pq,  g_q);
    cudaGetSymbolAddress((void**)&pk,  g_k);
    cudaGetSymbolAddress((void**)&pv,  g_v);
    cudaGetSymbolAddress((void**)&ph,  g_h);

    const int attn_smem = SM_FLOATS * 4;   // ~171 KB
    cudaFuncSetAttribute(attn_fused,
                         cudaFuncAttributeMaxDynamicSharedMemorySize, attn_smem);

    embed_kernel<<<BSn, 256>>>(inputs, emb);

    QKVArgs qa;
    qa.W[0] = q_w;  qa.W[1] = k_w;  qa.W[2] = v_w;
    qa.bias[0] = q_b; qa.bias[1] = k_b; qa.bias[2] = v_b;
    qa.out[0] = pq; qa.out[1] = pk; qa.out[2] = pv;

    for (int l = 0; l < 6; l++) {
        sgemm_qkv<<<dim3(En/128, BSn/128, 3), 256>>>(px, qa);

        vsum_kernel<<<(NBH*SKn*DHn + 255)/256, 256>>>();
        attn_fused<<<dim3(NQB, NBH), 256, attn_smem>>>();

        layernorm_kernel<<<BSn, 256>>>(px2, px, ln_w, ln_b);

        sgemm_ffn<<<dim3(HIDn/128, BSn/128), 256>>>(px, fc1_w, ph, fc1_b,
                                                    nullptr, En, HIDn, 1);
        sgemm_ffn<<<dim3(En/128, BSn/128), 256>>>(ph, fc2_w, px2, fc2_b,
                                                  px, HIDn, En, 2);

        layernorm_kernel<<<BSn, 256>>>(px2, px, ln_w, ln_b);
    }

    out_stage1<<<dim3(NCHUNK, Bn), 256>>>(out_w);
    out_stage2<<<1, 32>>>(out_b, out);
}